// round 12
// baseline (speedup 1.0000x reference)
#include <cuda_runtime.h>
#include <cuda_fp16.h>
#include <cstdint>

#define N_USER 50000
#define N_ITEM 100000
#define NTOT   150000
#define NNZ    3000000
#define EMB    64
#define BATCH  4096
#define NPAD   (NNZ + NTOT * 4 + 8)   // edges + worst-case per-row padding

// ---------------- device scratch (no allocation allowed) --------------------
__device__ __align__(16) __half2 g_egoA[(size_t)NTOT * 32];   // init ego, then layer-3 ego
__device__ __align__(16) __half2 g_egoB[(size_t)NTOT * 32];   // layer-1 ego
__device__ __align__(16) __half2 g_egoC[(size_t)NTOT * 32];   // layer-2 ego
__device__ float g_inv[3][NTOT];                              // per-layer inv norms
__device__ __align__(16) unsigned g_edges[(size_t)NPAD * 2];  // {col, valbits} pairs
__device__ int g_cnt[NTOT];     // zeroed by k_out at end of every call
__device__ int g_start[NTOT];
__device__ int g_cur[NTOT];
__device__ int g_ctr;           // zeroed by k_out at end of every call

// ---------------------------------------------------------------------------
// launch 0: fused init + histogram + edge-array zero. g_cnt/g_ctr zero at entry.
// ---------------------------------------------------------------------------
__global__ void k_init_hist(const float4* __restrict__ ue, const float4* __restrict__ ie,
                            const int* __restrict__ rows) {
    int i = blockIdx.x * blockDim.x + threadIdx.x;   // grid covers NNZ (3M)
    if (i < NTOT * 16) {
        float4 v = (i < N_USER * 16) ? ue[i] : ie[i - N_USER * 16];
        g_egoA[2 * i]     = __floats2half2_rn(v.x, v.y);
        g_egoA[2 * i + 1] = __floats2half2_rn(v.z, v.w);
    }
    uint2* ez = reinterpret_cast<uint2*>(g_edges);
    if (i < NPAD) ez[i] = make_uint2(0u, 0u);
    if (i + NNZ < NPAD) ez[i + NNZ] = make_uint2(0u, 0u);
    if (i < NNZ) atomicAdd(&g_cnt[rows[i]], 1);
}

// launch 1: atomic segment allocation, sizes rounded up to multiple of 4 edges
__global__ void k_alloc() {
    int r = blockIdx.x * blockDim.x + threadIdx.x;
    if (r >= NTOT) return;
    int c4 = (g_cnt[r] + 3) & ~3;
    int s = atomicAdd(&g_ctr, c4);
    g_start[r] = s;
    g_cur[r]   = s;
}

// launch 2: permute edges into row-grouped segments
__global__ void k_fill(const int* __restrict__ rows, const int* __restrict__ cols,
                       const float* __restrict__ vals) {
    int i = blockIdx.x * blockDim.x + threadIdx.x;
    if (i >= NNZ) return;
    int r = rows[i];
    int p = atomicAdd(&g_cur[r], 1);
    uint2* ez = reinterpret_cast<uint2*>(g_edges);
    ez[p] = make_uint2((unsigned)cols[i], __float_as_uint(vals[i]));
}

// ---------------------------------------------------------------------------
// launches 3-5: fused layer. Warp = 8 rows; lane owns cols {2l, 2l+1}.
// phase 1: clamp-free 4-wide gather per row (rows padded to x4, val=0 pads).
// srow layout [warp][l=k/2][r pad to 10][2]: per-l stride = 80B (16B multiple)
//   -> STS.64 per row (addr lane*80+r*8, ~4-way conflict)
//   -> phase-2 float4 broadcast reads at [l][0/2/4/6] are 16B-aligned.
// ---------------------------------------------------------------------------
__global__ void __launch_bounds__(256, 5)
k_layer(const __half2* __restrict__ ego_in, __half2* __restrict__ ego_out,
        float* __restrict__ inv_out,
        const float* __restrict__ W, const float* __restrict__ b) {
    __shared__ float Ws[EMB * EMB];
    __shared__ float srow[8][32][10][2];   // [warp][l][r(8 used,10 padded)][d]

    int tid = threadIdx.x;
    for (int i = tid; i < EMB * EMB / 4; i += 256)
        reinterpret_cast<float4*>(Ws)[i] = reinterpret_cast<const float4*>(W)[i];
    __syncthreads();

    int warp = tid >> 5, lane = tid & 31;
    int r0 = (blockIdx.x * 8 + warp) * 8;
    if (r0 >= NTOT) return;

    const __half2* egoL = ego_in + lane;   // per-lane base

    // ---- phase 1: segmented gather, 8 rows serial, clamp-free 4-wide ----
#pragma unroll
    for (int r = 0; r < 8; r++) {
        int row = r0 + r;
        float2 acc = make_float2(0.f, 0.f);
        int n4 = 0, s = 0;
        if (row < NTOT) { n4 = (g_cnt[row] + 3) & ~3; s = g_start[row]; }
        const uint4* ep = reinterpret_cast<const uint4*>(&g_edges[(size_t)s * 2]);

        for (int base = 0; base < n4; base += 4) {
            uint4 A = ep[(base >> 1)];
            uint4 B = ep[(base >> 1) + 1];
            __half2 x0 = egoL[(size_t)A.x * 32];
            __half2 x1 = egoL[(size_t)A.z * 32];
            __half2 x2 = egoL[(size_t)B.x * 32];
            __half2 x3 = egoL[(size_t)B.z * 32];
            float v0 = __uint_as_float(A.y);
            float v1 = __uint_as_float(A.w);
            float v2 = __uint_as_float(B.y);
            float v3 = __uint_as_float(B.w);
            float2 f0 = __half22float2(x0);
            float2 f1 = __half22float2(x1);
            float2 f2 = __half22float2(x2);
            float2 f3 = __half22float2(x3);
            acc.x += v0 * f0.x; acc.y += v0 * f0.y;
            acc.x += v1 * f1.x; acc.y += v1 * f1.y;
            acc.x += v2 * f2.x; acc.y += v2 * f2.y;
            acc.x += v3 * f3.x; acc.y += v3 * f3.y;
        }
        // acc = {side[2*lane], side[2*lane+1]} for this row -> one STS.64
        *reinterpret_cast<float2*>(&srow[warp][lane][r][0]) = acc;
    }
    __syncwarp();

    // ---- phase 2: batched 8-row matmul ----
    const float2 bias = *reinterpret_cast<const float2*>(&b[2 * lane]);
    float2 o[8];
#pragma unroll
    for (int r = 0; r < 8; r++) o[r] = bias;

#pragma unroll
    for (int l = 0; l < 32; l++) {
        // p0..p3: rows {0,1},{2,3},{4,5},{6,7}; .x/.y = row even {k=2l,2l+1},
        // .z/.w = row odd {k=2l,2l+1}. 16B-aligned broadcasts.
        float4 p0 = *reinterpret_cast<const float4*>(&srow[warp][l][0][0]);
        float4 p1 = *reinterpret_cast<const float4*>(&srow[warp][l][2][0]);
        float4 p2 = *reinterpret_cast<const float4*>(&srow[warp][l][4][0]);
        float4 p3 = *reinterpret_cast<const float4*>(&srow[warp][l][6][0]);
        float2 w0 = *reinterpret_cast<const float2*>(&Ws[(2 * l)     * EMB + 2 * lane]);
        float2 w1 = *reinterpret_cast<const float2*>(&Ws[(2 * l + 1) * EMB + 2 * lane]);
        o[0].x += p0.x * w0.x + p0.y * w1.x;  o[0].y += p0.x * w0.y + p0.y * w1.y;
        o[1].x += p0.z * w0.x + p0.w * w1.x;  o[1].y += p0.z * w0.y + p0.w * w1.y;
        o[2].x += p1.x * w0.x + p1.y * w1.x;  o[2].y += p1.x * w0.y + p1.y * w1.y;
        o[3].x += p1.z * w0.x + p1.w * w1.x;  o[3].y += p1.z * w0.y + p1.w * w1.y;
        o[4].x += p2.x * w0.x + p2.y * w1.x;  o[4].y += p2.x * w0.y + p2.y * w1.y;
        o[5].x += p2.z * w0.x + p2.w * w1.x;  o[5].y += p2.z * w0.y + p2.w * w1.y;
        o[6].x += p3.x * w0.x + p3.y * w1.x;  o[6].y += p3.x * w0.y + p3.y * w1.y;
        o[7].x += p3.z * w0.x + p3.w * w1.x;  o[7].y += p3.z * w0.y + p3.w * w1.y;
    }

    // ---- phase 3: leaky_relu -> fp16 ego_out + inv-norm ----
#pragma unroll
    for (int r = 0; r < 8; r++) {
        int row = r0 + r;
        if (row >= NTOT) break;
        float2 e;
        e.x = o[r].x > 0.f ? o[r].x : 0.2f * o[r].x;
        e.y = o[r].y > 0.f ? o[r].y : 0.2f * o[r].y;

        ego_out[(size_t)row * 32 + lane] = __floats2half2_rn(e.x, e.y);

        float ss = e.x * e.x + e.y * e.y;
#pragma unroll
        for (int off = 16; off; off >>= 1)
            ss += __shfl_xor_sync(0xffffffffu, ss, off);
        if (lane == 0)
            inv_out[row] = 1.f / fmaxf(sqrtf(ss), 1e-12f);
    }
}

// ---------------------------------------------------------------------------
// launch 6: out[u] = ue[u] + sum_l ego_l[u] * inv_l[u].
// Layer egos: B = layer1, C = layer2, A = layer3. Re-zeroes g_cnt / g_ctr.
// ---------------------------------------------------------------------------
__global__ void k_out(const int* __restrict__ users, const float* __restrict__ ue,
                      float* __restrict__ out) {
    int i = blockIdx.x * blockDim.x + threadIdx.x;
    if (i < NTOT) g_cnt[i] = 0;
    if (i == 0)   g_ctr = 0;
    if (i >= BATCH * EMB) return;
    int row = i >> 6, col = i & 63;
    int u = users[row];
    const __half* e1 = reinterpret_cast<const __half*>(g_egoB);
    const __half* e2 = reinterpret_cast<const __half*>(g_egoC);
    const __half* e3 = reinterpret_cast<const __half*>(g_egoA);
    size_t idx = (size_t)u * EMB + col;
    out[i] = ue[idx]
           + __half2float(e1[idx]) * g_inv[0][u]
           + __half2float(e2[idx]) * g_inv[1][u]
           + __half2float(e3[idx]) * g_inv[2][u];
}

// ---------------------------------------------------------------------------
extern "C" void kernel_launch(void* const* d_in, const int* in_sizes, int n_in,
                              void* d_out, int out_size) {
    const int*   users = (const int*)d_in[0];
    const int*   rows  = (const int*)d_in[1];
    const int*   cols  = (const int*)d_in[2];
    const float* vals  = (const float*)d_in[3];
    const float* ue    = (const float*)d_in[4];
    const float* ie    = (const float*)d_in[5];
    const float* Wl[3] = {(const float*)d_in[6], (const float*)d_in[8],  (const float*)d_in[10]};
    const float* Bl[3] = {(const float*)d_in[7], (const float*)d_in[9],  (const float*)d_in[11]};

    __half2 *egoA, *egoB, *egoC;
    float* invBase;
    cudaGetSymbolAddress((void**)&egoA, g_egoA);
    cudaGetSymbolAddress((void**)&egoB, g_egoB);
    cudaGetSymbolAddress((void**)&egoC, g_egoC);
    cudaGetSymbolAddress((void**)&invBase, g_inv);

    // 0: init + hist + edge-zero; 1: alloc (padded); 2: fill
    k_init_hist<<<(NNZ + 255) / 256, 256>>>((const float4*)ue, (const float4*)ie, rows);
    k_alloc<<<(NTOT + 255) / 256, 256>>>();
    k_fill<<<(NNZ + 255) / 256, 256>>>(rows, cols, vals);

    // 3-5: layers (64 rows per block)
    k_layer<<<(NTOT + 63) / 64, 256>>>(egoA, egoB, invBase + 0 * NTOT, Wl[0], Bl[0]);
    k_layer<<<(NTOT + 63) / 64, 256>>>(egoB, egoC, invBase + 1 * NTOT, Wl[1], Bl[1]);
    k_layer<<<(NTOT + 63) / 64, 256>>>(egoC, egoA, invBase + 2 * NTOT, Wl[2], Bl[2]);

    // 6: output gather + counter re-zero
    k_out<<<(BATCH * EMB + 255) / 256, 256>>>(users, ue, (float*)d_out);
}

// round 13
// speedup vs baseline: 1.0425x; 1.0425x over previous
#include <cuda_runtime.h>
#include <cuda_fp16.h>
#include <cstdint>

#define N_USER 50000
#define N_ITEM 100000
#define NTOT   150000
#define NNZ    3000000
#define EMB    64
#define BATCH  4096
#define NPAD   (NNZ + NTOT * 4 + 8)   // edges + worst-case per-row padding

// ---------------- device scratch (no allocation allowed) --------------------
__device__ __align__(16) __half2 g_egoA[(size_t)NTOT * 32];   // init ego, then layer-3 ego
__device__ __align__(16) __half2 g_egoB[(size_t)NTOT * 32];   // layer-1 ego
__device__ __align__(16) __half2 g_egoC[(size_t)NTOT * 32];   // layer-2 ego
__device__ __align__(16) float   g_side[(size_t)NTOT * EMB];  // fp32 side scratch
__device__ float g_inv[3][NTOT];                              // per-layer inv norms
__device__ __align__(16) unsigned g_edges[(size_t)NPAD * 2];  // {col, valbits} pairs
__device__ int g_cnt[NTOT];     // zeroed by k_out at end of every call
__device__ int g_start[NTOT];
__device__ int g_cur[NTOT];
__device__ int g_ctr;           // zeroed by k_out at end of every call

// ---------------------------------------------------------------------------
// launch 0: fused init + histogram + edge-array zero. g_cnt/g_ctr zero at entry.
// ---------------------------------------------------------------------------
__global__ void k_init_hist(const float4* __restrict__ ue, const float4* __restrict__ ie,
                            const int* __restrict__ rows) {
    int i = blockIdx.x * blockDim.x + threadIdx.x;   // grid covers NNZ (3M)
    if (i < NTOT * 16) {
        float4 v = (i < N_USER * 16) ? ue[i] : ie[i - N_USER * 16];
        g_egoA[2 * i]     = __floats2half2_rn(v.x, v.y);
        g_egoA[2 * i + 1] = __floats2half2_rn(v.z, v.w);
    }
    uint2* ez = reinterpret_cast<uint2*>(g_edges);
    if (i < NPAD) ez[i] = make_uint2(0u, 0u);
    if (i + NNZ < NPAD) ez[i + NNZ] = make_uint2(0u, 0u);
    if (i < NNZ) atomicAdd(&g_cnt[rows[i]], 1);
}

// launch 1: atomic segment allocation, sizes rounded up to multiple of 4 edges
__global__ void k_alloc() {
    int r = blockIdx.x * blockDim.x + threadIdx.x;
    if (r >= NTOT) return;
    int c4 = (g_cnt[r] + 3) & ~3;
    int s = atomicAdd(&g_ctr, c4);
    g_start[r] = s;
    g_cur[r]   = s;
}

// launch 2: permute edges into row-grouped segments
__global__ void k_fill(const int* __restrict__ rows, const int* __restrict__ cols,
                       const float* __restrict__ vals) {
    int i = blockIdx.x * blockDim.x + threadIdx.x;
    if (i >= NNZ) return;
    int r = rows[i];
    int p = atomicAdd(&g_cur[r], 1);
    uint2* ez = reinterpret_cast<uint2*>(g_edges);
    ez[p] = make_uint2((unsigned)cols[i], __float_as_uint(vals[i]));
}

// ---------------------------------------------------------------------------
// gather kernel: ZERO smem, minimal regs -> 8 blocks/SM (100% occupancy).
// Warp = 4 rows serial; lane owns cols {2l,2l+1}; clamp-free 4-wide loop
// (rows padded to x4 with val=0 edges). Writes side row as coalesced STG.64.
// ---------------------------------------------------------------------------
__global__ void __launch_bounds__(256, 8)
k_gather(const __half2* __restrict__ ego_in) {
    int tid  = threadIdx.x;
    int warp = tid >> 5, lane = tid & 31;
    int r0 = (blockIdx.x * 8 + warp) * 4;
    if (r0 >= NTOT) return;

    const __half2* egoL = ego_in + lane;

#pragma unroll
    for (int r = 0; r < 4; r++) {
        int row = r0 + r;
        if (row >= NTOT) break;
        float2 acc = make_float2(0.f, 0.f);
        int n4 = (g_cnt[row] + 3) & ~3;
        int s  = g_start[row];
        const uint4* ep = reinterpret_cast<const uint4*>(&g_edges[(size_t)s * 2]);

        for (int base = 0; base < n4; base += 4) {
            uint4 A = ep[(base >> 1)];
            uint4 B = ep[(base >> 1) + 1];
            __half2 x0 = egoL[(size_t)A.x * 32];
            __half2 x1 = egoL[(size_t)A.z * 32];
            __half2 x2 = egoL[(size_t)B.x * 32];
            __half2 x3 = egoL[(size_t)B.z * 32];
            float v0 = __uint_as_float(A.y);
            float v1 = __uint_as_float(A.w);
            float v2 = __uint_as_float(B.y);
            float v3 = __uint_as_float(B.w);
            float2 f0 = __half22float2(x0);
            float2 f1 = __half22float2(x1);
            float2 f2 = __half22float2(x2);
            float2 f3 = __half22float2(x3);
            acc.x += v0 * f0.x; acc.y += v0 * f0.y;
            acc.x += v1 * f1.x; acc.y += v1 * f1.y;
            acc.x += v2 * f2.x; acc.y += v2 * f2.y;
            acc.x += v3 * f3.x; acc.y += v3 * f3.y;
        }
        *reinterpret_cast<float2*>(&g_side[(size_t)row * EMB + 2 * lane]) = acc;
    }
}

// ---------------------------------------------------------------------------
// dense kernel: warp = 8 rows. Loads side rows (coalesced), stages via the
// R12 srow layout (stride 80B: STS.64 stores, 16B-aligned float4 bcast reads),
// 8-row batched matmul, leaky_relu -> fp16 ego_out + inv-norm.
// ---------------------------------------------------------------------------
__global__ void __launch_bounds__(256, 5)
k_dense(__half2* __restrict__ ego_out, float* __restrict__ inv_out,
        const float* __restrict__ W, const float* __restrict__ b) {
    __shared__ float Ws[EMB * EMB];
    __shared__ float srow[8][32][10][2];   // [warp][l][r(8 used,10 padded)][d]

    int tid = threadIdx.x;
    for (int i = tid; i < EMB * EMB / 4; i += 256)
        reinterpret_cast<float4*>(Ws)[i] = reinterpret_cast<const float4*>(W)[i];
    __syncthreads();

    int warp = tid >> 5, lane = tid & 31;
    int r0 = (blockIdx.x * 8 + warp) * 8;
    if (r0 >= NTOT) return;

    // stage 8 side rows: lane loads cols {2l,2l+1} -> STS.64
#pragma unroll
    for (int r = 0; r < 8; r++) {
        int row = r0 + r;
        float2 v = make_float2(0.f, 0.f);
        if (row < NTOT)
            v = *reinterpret_cast<const float2*>(&g_side[(size_t)row * EMB + 2 * lane]);
        *reinterpret_cast<float2*>(&srow[warp][lane][r][0]) = v;
    }
    __syncwarp();

    const float2 bias = *reinterpret_cast<const float2*>(&b[2 * lane]);
    float2 o[8];
#pragma unroll
    for (int r = 0; r < 8; r++) o[r] = bias;

#pragma unroll
    for (int l = 0; l < 32; l++) {
        float4 p0 = *reinterpret_cast<const float4*>(&srow[warp][l][0][0]);
        float4 p1 = *reinterpret_cast<const float4*>(&srow[warp][l][2][0]);
        float4 p2 = *reinterpret_cast<const float4*>(&srow[warp][l][4][0]);
        float4 p3 = *reinterpret_cast<const float4*>(&srow[warp][l][6][0]);
        float2 w0 = *reinterpret_cast<const float2*>(&Ws[(2 * l)     * EMB + 2 * lane]);
        float2 w1 = *reinterpret_cast<const float2*>(&Ws[(2 * l + 1) * EMB + 2 * lane]);
        o[0].x += p0.x * w0.x + p0.y * w1.x;  o[0].y += p0.x * w0.y + p0.y * w1.y;
        o[1].x += p0.z * w0.x + p0.w * w1.x;  o[1].y += p0.z * w0.y + p0.w * w1.y;
        o[2].x += p1.x * w0.x + p1.y * w1.x;  o[2].y += p1.x * w0.y + p1.y * w1.y;
        o[3].x += p1.z * w0.x + p1.w * w1.x;  o[3].y += p1.z * w0.y + p1.w * w1.y;
        o[4].x += p2.x * w0.x + p2.y * w1.x;  o[4].y += p2.x * w0.y + p2.y * w1.y;
        o[5].x += p2.z * w0.x + p2.w * w1.x;  o[5].y += p2.z * w0.y + p2.w * w1.y;
        o[6].x += p3.x * w0.x + p3.y * w1.x;  o[6].y += p3.x * w0.y + p3.y * w1.y;
        o[7].x += p3.z * w0.x + p3.w * w1.x;  o[7].y += p3.z * w0.y + p3.w * w1.y;
    }

#pragma unroll
    for (int r = 0; r < 8; r++) {
        int row = r0 + r;
        if (row >= NTOT) break;
        float2 e;
        e.x = o[r].x > 0.f ? o[r].x : 0.2f * o[r].x;
        e.y = o[r].y > 0.f ? o[r].y : 0.2f * o[r].y;

        ego_out[(size_t)row * 32 + lane] = __floats2half2_rn(e.x, e.y);

        float ss = e.x * e.x + e.y * e.y;
#pragma unroll
        for (int off = 16; off; off >>= 1)
            ss += __shfl_xor_sync(0xffffffffu, ss, off);
        if (lane == 0)
            inv_out[row] = 1.f / fmaxf(sqrtf(ss), 1e-12f);
    }
}

// ---------------------------------------------------------------------------
// final launch: out[u] = ue[u] + sum_l ego_l[u] * inv_l[u].
// Layer egos: B = layer1, C = layer2, A = layer3. Re-zeroes g_cnt / g_ctr.
// ---------------------------------------------------------------------------
__global__ void k_out(const int* __restrict__ users, const float* __restrict__ ue,
                      float* __restrict__ out) {
    int i = blockIdx.x * blockDim.x + threadIdx.x;
    if (i < NTOT) g_cnt[i] = 0;
    if (i == 0)   g_ctr = 0;
    if (i >= BATCH * EMB) return;
    int row = i >> 6, col = i & 63;
    int u = users[row];
    const __half* e1 = reinterpret_cast<const __half*>(g_egoB);
    const __half* e2 = reinterpret_cast<const __half*>(g_egoC);
    const __half* e3 = reinterpret_cast<const __half*>(g_egoA);
    size_t idx = (size_t)u * EMB + col;
    out[i] = ue[idx]
           + __half2float(e1[idx]) * g_inv[0][u]
           + __half2float(e2[idx]) * g_inv[1][u]
           + __half2float(e3[idx]) * g_inv[2][u];
}

// ---------------------------------------------------------------------------
extern "C" void kernel_launch(void* const* d_in, const int* in_sizes, int n_in,
                              void* d_out, int out_size) {
    const int*   users = (const int*)d_in[0];
    const int*   rows  = (const int*)d_in[1];
    const int*   cols  = (const int*)d_in[2];
    const float* vals  = (const float*)d_in[3];
    const float* ue    = (const float*)d_in[4];
    const float* ie    = (const float*)d_in[5];
    const float* Wl[3] = {(const float*)d_in[6], (const float*)d_in[8],  (const float*)d_in[10]};
    const float* Bl[3] = {(const float*)d_in[7], (const float*)d_in[9],  (const float*)d_in[11]};

    __half2 *egoA, *egoB, *egoC;
    float* invBase;
    cudaGetSymbolAddress((void**)&egoA, g_egoA);
    cudaGetSymbolAddress((void**)&egoB, g_egoB);
    cudaGetSymbolAddress((void**)&egoC, g_egoC);
    cudaGetSymbolAddress((void**)&invBase, g_inv);

    // 0: init + hist + edge-zero; 1: alloc (padded); 2: fill
    k_init_hist<<<(NNZ + 255) / 256, 256>>>((const float4*)ue, (const float4*)ie, rows);
    k_alloc<<<(NTOT + 255) / 256, 256>>>();
    k_fill<<<(NNZ + 255) / 256, 256>>>(rows, cols, vals);

    // layers: gather (launch #3 profiled) + dense, x3
    const int GG = (NTOT + 31) / 32;   // gather: 32 rows/block
    const int GD = (NTOT + 63) / 64;   // dense: 64 rows/block
    k_gather<<<GG, 256>>>(egoA);
    k_dense <<<GD, 256>>>(egoB, invBase + 0 * NTOT, Wl[0], Bl[0]);
    k_gather<<<GG, 256>>>(egoB);
    k_dense <<<GD, 256>>>(egoC, invBase + 1 * NTOT, Wl[1], Bl[1]);
    k_gather<<<GG, 256>>>(egoC);
    k_dense <<<GD, 256>>>(egoA, invBase + 2 * NTOT, Wl[2], Bl[2]);

    // output gather + counter re-zero
    k_out<<<(BATCH * EMB + 255) / 256, 256>>>(users, ue, (float*)d_out);
}

// round 14
// speedup vs baseline: 1.3475x; 1.2926x over previous
#include <cuda_runtime.h>
#include <cuda_fp16.h>
#include <cstdint>

#define N_USER 50000
#define N_ITEM 100000
#define NTOT   150000
#define NTOTP  150016            // padded to multiple of 128 (dense block rows)
#define NNZ    3000000
#define EMB    64
#define BATCH  4096
#define NPAD   (NNZ + NTOT * 4 + 8)

// ---------------- device scratch (no allocation allowed) --------------------
__device__ __align__(16) __half2 g_egoA[(size_t)NTOTP * 32];  // init ego, then layer-3 ego
__device__ __align__(16) __half2 g_egoB[(size_t)NTOTP * 32];  // layer-1 ego
__device__ __align__(16) __half2 g_egoC[(size_t)NTOTP * 32];  // layer-2 ego
__device__ __align__(16) __half2 g_side16[(size_t)NTOTP * 32];// fp16 side scratch
__device__ float g_inv[3][NTOTP];                             // per-layer inv norms
__device__ __align__(16) unsigned g_edges[(size_t)NPAD * 2];  // {col, valbits} pairs
__device__ int g_cnt[NTOT];     // zeroed by k_out at end of every call
__device__ int g_start[NTOT];
__device__ int g_cur[NTOT];
__device__ int g_ctr;           // zeroed by k_out at end of every call

// ---------------------------------------------------------------------------
// launch 0: fused init + histogram. (No blanket edge zero: pad slots are
// written by k_alloc.) g_cnt/g_ctr zero at entry.
// ---------------------------------------------------------------------------
__global__ void k_init_hist(const float4* __restrict__ ue, const float4* __restrict__ ie,
                            const int* __restrict__ rows) {
    int i = blockIdx.x * blockDim.x + threadIdx.x;   // grid covers NNZ (3M)
    if (i < NTOT * 16) {
        float4 v = (i < N_USER * 16) ? ue[i] : ie[i - N_USER * 16];
        g_egoA[2 * i]     = __floats2half2_rn(v.x, v.y);
        g_egoA[2 * i + 1] = __floats2half2_rn(v.z, v.w);
    }
    if (i < NNZ) atomicAdd(&g_cnt[rows[i]], 1);
}

// launch 1: atomic segment allocation (x4-padded); writes {0,0} pad edges.
__global__ void k_alloc() {
    int r = blockIdx.x * blockDim.x + threadIdx.x;
    if (r >= NTOT) return;
    int cnt = g_cnt[r];
    int c4  = (cnt + 3) & ~3;
    int s = atomicAdd(&g_ctr, c4);
    g_start[r] = s;
    g_cur[r]   = s;
    uint2* ez = reinterpret_cast<uint2*>(g_edges);
    for (int j = cnt; j < c4; j++) ez[s + j] = make_uint2(0u, 0u);
}

// launch 2: permute edges into row-grouped segments
__global__ void k_fill(const int* __restrict__ rows, const int* __restrict__ cols,
                       const float* __restrict__ vals) {
    int i = blockIdx.x * blockDim.x + threadIdx.x;
    if (i >= NNZ) return;
    int r = rows[i];
    int p = atomicAdd(&g_cur[r], 1);
    uint2* ez = reinterpret_cast<uint2*>(g_edges);
    ez[p] = make_uint2((unsigned)cols[i], __float_as_uint(vals[i]));
}

// ---------------------------------------------------------------------------
// gather: zero smem, 32 regs -> 8 blocks/SM. Warp = 4 rows serial; lane owns
// cols {2l,2l+1}; clamp-free 4-wide (rows padded x4, val=0 pads). fp16 side out.
// ---------------------------------------------------------------------------
__global__ void __launch_bounds__(256, 8)
k_gather(const __half2* __restrict__ ego_in) {
    int tid  = threadIdx.x;
    int warp = tid >> 5, lane = tid & 31;
    int r0 = (blockIdx.x * 8 + warp) * 4;
    if (r0 >= NTOT) return;

    const __half2* egoL = ego_in + lane;

#pragma unroll
    for (int r = 0; r < 4; r++) {
        int row = r0 + r;
        if (row >= NTOT) break;
        float2 acc = make_float2(0.f, 0.f);
        int n4 = (g_cnt[row] + 3) & ~3;
        int s  = g_start[row];
        const uint4* ep = reinterpret_cast<const uint4*>(&g_edges[(size_t)s * 2]);

        for (int base = 0; base < n4; base += 4) {
            uint4 A = ep[(base >> 1)];
            uint4 B = ep[(base >> 1) + 1];
            __half2 x0 = egoL[(size_t)A.x * 32];
            __half2 x1 = egoL[(size_t)A.z * 32];
            __half2 x2 = egoL[(size_t)B.x * 32];
            __half2 x3 = egoL[(size_t)B.z * 32];
            float v0 = __uint_as_float(A.y);
            float v1 = __uint_as_float(A.w);
            float v2 = __uint_as_float(B.y);
            float v3 = __uint_as_float(B.w);
            float2 f0 = __half22float2(x0);
            float2 f1 = __half22float2(x1);
            float2 f2 = __half22float2(x2);
            float2 f3 = __half22float2(x3);
            acc.x += v0 * f0.x; acc.y += v0 * f0.y;
            acc.x += v1 * f1.x; acc.y += v1 * f1.y;
            acc.x += v2 * f2.x; acc.y += v2 * f2.y;
            acc.x += v3 * f3.x; acc.y += v3 * f3.y;
        }
        g_side16[(size_t)row * 32 + lane] = __floats2half2_rn(acc.x, acc.y);
    }
}

// ---------------------------------------------------------------------------
// dense via tensor cores: mma.sync.m16n8k16 (fp16 in, fp32 accum).
// Block = 8 warps x 16 rows = 128 rows. A frags loaded directly from global
// fp16 side (each (row, 2k) pair is one aligned half2 word). B = W^T in smem
// fp16 [64][72] (pad 72 -> conflict-free: bank == lane). Bias in accum init.
// Epilogue: leaky_relu, fp16 ego store, row norm via 2x shfl_xor in 4-lane group.
// ---------------------------------------------------------------------------
__global__ void __launch_bounds__(256, 4)
k_dense(__half2* __restrict__ ego_out, float* __restrict__ inv_out,
        const float* __restrict__ W, const float* __restrict__ b) {
    __shared__ __half Wt[64][72];   // Wt[n][k] = W[k][n]

    int tid = threadIdx.x;
    for (int i = tid; i < EMB * EMB; i += 256) {
        int k = i >> 6, n = i & 63;
        Wt[n][k] = __float2half(W[i]);      // coalesced read, scattered STS
    }
    __syncthreads();

    int t = tid & 31, w = tid >> 5;
    int g = t >> 2, q = t & 3;              // group (n / row) , quad (k / col)
    int r0 = blockIdx.x * 128 + w * 16 + g; // rows r0 and r0+8 (< NTOTP always)

    const unsigned* S0 = reinterpret_cast<const unsigned*>(g_side16) + (size_t)r0 * 32;
    const unsigned* S1 = S0 + 8 * 32;

    // accumulators: c[nn] = {d(r0,c), d(r0,c+1), d(r0+8,c), d(r0+8,c+1)},
    // c = nn*8 + 2q. Init with bias (same cols both rows).
    float c[8][4];
#pragma unroll
    for (int nn = 0; nn < 8; nn++) {
        float2 bb = *reinterpret_cast<const float2*>(&b[nn * 8 + 2 * q]);
        c[nn][0] = bb.x; c[nn][1] = bb.y; c[nn][2] = bb.x; c[nn][3] = bb.y;
    }

#pragma unroll
    for (int kk = 0; kk < 4; kk++) {
        unsigned a0 = S0[kk * 8 + q];        // (r0,   k: kk*16+2q, +1)
        unsigned a1 = S1[kk * 8 + q];        // (r0+8, same k)
        unsigned a2 = S0[kk * 8 + q + 4];    // (r0,   k+8)
        unsigned a3 = S1[kk * 8 + q + 4];    // (r0+8, k+8)
#pragma unroll
        for (int nn = 0; nn < 8; nn++) {
            int n = nn * 8 + g;
            unsigned b0 = *reinterpret_cast<const unsigned*>(&Wt[n][kk * 16 + 2 * q]);
            unsigned b1 = *reinterpret_cast<const unsigned*>(&Wt[n][kk * 16 + 2 * q + 8]);
            asm volatile(
                "mma.sync.aligned.m16n8k16.row.col.f32.f16.f16.f32 "
                "{%0,%1,%2,%3}, {%4,%5,%6,%7}, {%8,%9}, {%0,%1,%2,%3};"
                : "+f"(c[nn][0]), "+f"(c[nn][1]), "+f"(c[nn][2]), "+f"(c[nn][3])
                : "r"(a0), "r"(a1), "r"(a2), "r"(a3), "r"(b0), "r"(b1));
        }
    }

    // epilogue
    float ssl = 0.f, ssh = 0.f;
#pragma unroll
    for (int nn = 0; nn < 8; nn++) {
        float e0 = c[nn][0] > 0.f ? c[nn][0] : 0.2f * c[nn][0];
        float e1 = c[nn][1] > 0.f ? c[nn][1] : 0.2f * c[nn][1];
        float e2 = c[nn][2] > 0.f ? c[nn][2] : 0.2f * c[nn][2];
        float e3 = c[nn][3] > 0.f ? c[nn][3] : 0.2f * c[nn][3];
        ego_out[(size_t)r0 * 32       + nn * 4 + q] = __floats2half2_rn(e0, e1);
        ego_out[(size_t)(r0 + 8) * 32 + nn * 4 + q] = __floats2half2_rn(e2, e3);
        ssl += e0 * e0 + e1 * e1;
        ssh += e2 * e2 + e3 * e3;
    }
    ssl += __shfl_xor_sync(0xffffffffu, ssl, 1);
    ssl += __shfl_xor_sync(0xffffffffu, ssl, 2);
    ssh += __shfl_xor_sync(0xffffffffu, ssh, 1);
    ssh += __shfl_xor_sync(0xffffffffu, ssh, 2);
    if (q == 0) {
        inv_out[r0]     = 1.f / fmaxf(sqrtf(ssl), 1e-12f);
        inv_out[r0 + 8] = 1.f / fmaxf(sqrtf(ssh), 1e-12f);
    }
}

// ---------------------------------------------------------------------------
// final launch: out[u] = ue[u] + sum_l ego_l[u] * inv_l[u].
// Egos: B = layer1, C = layer2, A = layer3. Re-zeroes g_cnt / g_ctr.
// ---------------------------------------------------------------------------
__global__ void k_out(const int* __restrict__ users, const float* __restrict__ ue,
                      float* __restrict__ out) {
    int i = blockIdx.x * blockDim.x + threadIdx.x;
    if (i < NTOT) g_cnt[i] = 0;
    if (i == 0)   g_ctr = 0;
    if (i >= BATCH * EMB) return;
    int row = i >> 6, col = i & 63;
    int u = users[row];
    const __half* e1 = reinterpret_cast<const __half*>(g_egoB);
    const __half* e2 = reinterpret_cast<const __half*>(g_egoC);
    const __half* e3 = reinterpret_cast<const __half*>(g_egoA);
    size_t idx = (size_t)u * EMB + col;
    out[i] = ue[idx]
           + __half2float(e1[idx]) * g_inv[0][u]
           + __half2float(e2[idx]) * g_inv[1][u]
           + __half2float(e3[idx]) * g_inv[2][u];
}

// ---------------------------------------------------------------------------
extern "C" void kernel_launch(void* const* d_in, const int* in_sizes, int n_in,
                              void* d_out, int out_size) {
    const int*   users = (const int*)d_in[0];
    const int*   rows  = (const int*)d_in[1];
    const int*   cols  = (const int*)d_in[2];
    const float* vals  = (const float*)d_in[3];
    const float* ue    = (const float*)d_in[4];
    const float* ie    = (const float*)d_in[5];
    const float* Wl[3] = {(const float*)d_in[6], (const float*)d_in[8],  (const float*)d_in[10]};
    const float* Bl[3] = {(const float*)d_in[7], (const float*)d_in[9],  (const float*)d_in[11]};

    __half2 *egoA, *egoB, *egoC;
    float* invBase;
    cudaGetSymbolAddress((void**)&egoA, g_egoA);
    cudaGetSymbolAddress((void**)&egoB, g_egoB);
    cudaGetSymbolAddress((void**)&egoC, g_egoC);
    cudaGetSymbolAddress((void**)&invBase, g_inv);

    // 0: init + hist; 1: alloc (+pad edges); 2: fill
    k_init_hist<<<(NNZ + 255) / 256, 256>>>((const float4*)ue, (const float4*)ie, rows);
    k_alloc<<<(NTOT + 255) / 256, 256>>>();
    k_fill<<<(NNZ + 255) / 256, 256>>>(rows, cols, vals);

    // layers: gather (launch #3 profiled) + tensor-core dense, x3
    const int GG = (NTOT + 31) / 32;     // gather: 32 rows/block
    const int GD = NTOTP / 128;          // dense: 128 rows/block
    k_gather<<<GG, 256>>>(egoA);
    k_dense <<<GD, 256>>>(egoB, invBase + 0 * NTOTP, Wl[0], Bl[0]);
    k_gather<<<GG, 256>>>(egoB);
    k_dense <<<GD, 256>>>(egoC, invBase + 1 * NTOTP, Wl[1], Bl[1]);
    k_gather<<<GG, 256>>>(egoC);
    k_dense <<<GD, 256>>>(egoA, invBase + 2 * NTOTP, Wl[2], Bl[2]);

    // output gather + counter re-zero
    k_out<<<(BATCH * EMB + 255) / 256, 256>>>(users, ue, (float*)d_out);
}

// round 15
// speedup vs baseline: 1.3546x; 1.0052x over previous
#include <cuda_runtime.h>
#include <cuda_fp16.h>
#include <cstdint>

#define N_USER 50000
#define N_ITEM 100000
#define NTOT   150000
#define NTOTP  150016            // padded to multiple of 128 (dense block rows)
#define NNZ    3000000
#define EMB    64
#define BATCH  4096
#define NPAD   (NNZ + NTOT * 8 + 16)   // edges + worst-case per-row pad (x8)

// ---------------- device scratch (no allocation allowed) --------------------
__device__ __align__(16) __half2 g_egoA[(size_t)NTOTP * 32];  // init ego, then layer-3 ego
__device__ __align__(16) __half2 g_egoB[(size_t)NTOTP * 32];  // layer-1 ego
__device__ __align__(16) __half2 g_egoC[(size_t)NTOTP * 32];  // layer-2 ego
__device__ __align__(16) __half2 g_side16[(size_t)NTOTP * 32];// fp16 side scratch
__device__ float g_inv[3][NTOTP];                             // per-layer inv norms
__device__ __align__(16) unsigned g_edges[(size_t)NPAD * 2];  // {col, valbits} pairs
__device__ int g_cnt[NTOT];     // zeroed by k_out at end of every call
__device__ int g_start[NTOT];
__device__ int g_cur[NTOT];
__device__ int g_ctr;           // zeroed by k_out at end of every call

// ---------------------------------------------------------------------------
// launch 0: fused init + histogram. g_cnt/g_ctr zero at entry.
// ---------------------------------------------------------------------------
__global__ void k_init_hist(const float4* __restrict__ ue, const float4* __restrict__ ie,
                            const int* __restrict__ rows) {
    int i = blockIdx.x * blockDim.x + threadIdx.x;   // grid covers NNZ (3M)
    if (i < NTOT * 16) {
        float4 v = (i < N_USER * 16) ? ue[i] : ie[i - N_USER * 16];
        g_egoA[2 * i]     = __floats2half2_rn(v.x, v.y);
        g_egoA[2 * i + 1] = __floats2half2_rn(v.z, v.w);
    }
    if (i < NNZ) atomicAdd(&g_cnt[rows[i]], 1);
}

// launch 1: atomic segment allocation (x8-padded); writes {0,0} pad edges.
__global__ void k_alloc() {
    int r = blockIdx.x * blockDim.x + threadIdx.x;
    if (r >= NTOT) return;
    int cnt = g_cnt[r];
    int c8  = (cnt + 7) & ~7;
    int s = atomicAdd(&g_ctr, c8);
    g_start[r] = s;
    g_cur[r]   = s;
    uint2* ez = reinterpret_cast<uint2*>(g_edges);
    for (int j = cnt; j < c8; j++) ez[s + j] = make_uint2(0u, 0u);
}

// launch 2: permute edges into row-grouped segments
__global__ void k_fill(const int* __restrict__ rows, const int* __restrict__ cols,
                       const float* __restrict__ vals) {
    int i = blockIdx.x * blockDim.x + threadIdx.x;
    if (i >= NNZ) return;
    int r = rows[i];
    int p = atomicAdd(&g_cur[r], 1);
    uint2* ez = reinterpret_cast<uint2*>(g_edges);
    ez[p] = make_uint2((unsigned)cols[i], __float_as_uint(vals[i]));
}

// ---------------------------------------------------------------------------
// gather: zero smem, 8-wide clamp-free chunks (rows padded x8, val=0 pads).
// Warp = 4 rows serial; lane owns cols {2l,2l+1}. 4 uint4 edge loads + 8
// independent gathers in flight per chunk. launch_bounds(256,6) -> <=42 regs.
// ---------------------------------------------------------------------------
__global__ void __launch_bounds__(256, 6)
k_gather(const __half2* __restrict__ ego_in) {
    int tid  = threadIdx.x;
    int warp = tid >> 5, lane = tid & 31;
    int r0 = (blockIdx.x * 8 + warp) * 4;
    if (r0 >= NTOT) return;

    const __half2* egoL = ego_in + lane;

#pragma unroll
    for (int r = 0; r < 4; r++) {
        int row = r0 + r;
        if (row >= NTOT) break;
        float2 acc = make_float2(0.f, 0.f);
        int n8 = (g_cnt[row] + 7) & ~7;
        int s  = g_start[row];
        const uint4* ep = reinterpret_cast<const uint4*>(&g_edges[(size_t)s * 2]);

        for (int base = 0; base < n8; base += 8) {
            int h = base >> 1;
            uint4 A = ep[h];
            uint4 B = ep[h + 1];
            uint4 C = ep[h + 2];
            uint4 D = ep[h + 3];
            __half2 x0 = egoL[(size_t)A.x * 32];
            __half2 x1 = egoL[(size_t)A.z * 32];
            __half2 x2 = egoL[(size_t)B.x * 32];
            __half2 x3 = egoL[(size_t)B.z * 32];
            __half2 x4 = egoL[(size_t)C.x * 32];
            __half2 x5 = egoL[(size_t)C.z * 32];
            __half2 x6 = egoL[(size_t)D.x * 32];
            __half2 x7 = egoL[(size_t)D.z * 32];
            float v0 = __uint_as_float(A.y);
            float v1 = __uint_as_float(A.w);
            float v2 = __uint_as_float(B.y);
            float v3 = __uint_as_float(B.w);
            float v4 = __uint_as_float(C.y);
            float v5 = __uint_as_float(C.w);
            float v6 = __uint_as_float(D.y);
            float v7 = __uint_as_float(D.w);
            float2 f0 = __half22float2(x0);
            float2 f1 = __half22float2(x1);
            float2 f2 = __half22float2(x2);
            float2 f3 = __half22float2(x3);
            float2 f4 = __half22float2(x4);
            float2 f5 = __half22float2(x5);
            float2 f6 = __half22float2(x6);
            float2 f7 = __half22float2(x7);
            acc.x += v0 * f0.x; acc.y += v0 * f0.y;
            acc.x += v1 * f1.x; acc.y += v1 * f1.y;
            acc.x += v2 * f2.x; acc.y += v2 * f2.y;
            acc.x += v3 * f3.x; acc.y += v3 * f3.y;
            acc.x += v4 * f4.x; acc.y += v4 * f4.y;
            acc.x += v5 * f5.x; acc.y += v5 * f5.y;
            acc.x += v6 * f6.x; acc.y += v6 * f6.y;
            acc.x += v7 * f7.x; acc.y += v7 * f7.y;
        }
        g_side16[(size_t)row * 32 + lane] = __floats2half2_rn(acc.x, acc.y);
    }
}

// ---------------------------------------------------------------------------
// dense via tensor cores: mma.sync.m16n8k16 (fp16 in, fp32 accum).
// Block = 8 warps x 16 rows = 128 rows. A frags from global fp16 side.
// B = W^T in smem fp16 [64][72]. Bias in accum init. Epilogue: leaky_relu,
// fp16 ego store, row norm via 2x shfl_xor in 4-lane group.
// ---------------------------------------------------------------------------
__global__ void __launch_bounds__(256, 4)
k_dense(__half2* __restrict__ ego_out, float* __restrict__ inv_out,
        const float* __restrict__ W, const float* __restrict__ b) {
    __shared__ __half Wt[64][72];   // Wt[n][k] = W[k][n]

    int tid = threadIdx.x;
    for (int i = tid; i < EMB * EMB; i += 256) {
        int k = i >> 6, n = i & 63;
        Wt[n][k] = __float2half(W[i]);
    }
    __syncthreads();

    int t = tid & 31, w = tid >> 5;
    int g = t >> 2, q = t & 3;
    int r0 = blockIdx.x * 128 + w * 16 + g;

    const unsigned* S0 = reinterpret_cast<const unsigned*>(g_side16) + (size_t)r0 * 32;
    const unsigned* S1 = S0 + 8 * 32;

    float c[8][4];
#pragma unroll
    for (int nn = 0; nn < 8; nn++) {
        float2 bb = *reinterpret_cast<const float2*>(&b[nn * 8 + 2 * q]);
        c[nn][0] = bb.x; c[nn][1] = bb.y; c[nn][2] = bb.x; c[nn][3] = bb.y;
    }

#pragma unroll
    for (int kk = 0; kk < 4; kk++) {
        unsigned a0 = S0[kk * 8 + q];
        unsigned a1 = S1[kk * 8 + q];
        unsigned a2 = S0[kk * 8 + q + 4];
        unsigned a3 = S1[kk * 8 + q + 4];
#pragma unroll
        for (int nn = 0; nn < 8; nn++) {
            int n = nn * 8 + g;
            unsigned b0 = *reinterpret_cast<const unsigned*>(&Wt[n][kk * 16 + 2 * q]);
            unsigned b1 = *reinterpret_cast<const unsigned*>(&Wt[n][kk * 16 + 2 * q + 8]);
            asm volatile(
                "mma.sync.aligned.m16n8k16.row.col.f32.f16.f16.f32 "
                "{%0,%1,%2,%3}, {%4,%5,%6,%7}, {%8,%9}, {%0,%1,%2,%3};"
                : "+f"(c[nn][0]), "+f"(c[nn][1]), "+f"(c[nn][2]), "+f"(c[nn][3])
                : "r"(a0), "r"(a1), "r"(a2), "r"(a3), "r"(b0), "r"(b1));
        }
    }

    float ssl = 0.f, ssh = 0.f;
#pragma unroll
    for (int nn = 0; nn < 8; nn++) {
        float e0 = c[nn][0] > 0.f ? c[nn][0] : 0.2f * c[nn][0];
        float e1 = c[nn][1] > 0.f ? c[nn][1] : 0.2f * c[nn][1];
        float e2 = c[nn][2] > 0.f ? c[nn][2] : 0.2f * c[nn][2];
        float e3 = c[nn][3] > 0.f ? c[nn][3] : 0.2f * c[nn][3];
        ego_out[(size_t)r0 * 32       + nn * 4 + q] = __floats2half2_rn(e0, e1);
        ego_out[(size_t)(r0 + 8) * 32 + nn * 4 + q] = __floats2half2_rn(e2, e3);
        ssl += e0 * e0 + e1 * e1;
        ssh += e2 * e2 + e3 * e3;
    }
    ssl += __shfl_xor_sync(0xffffffffu, ssl, 1);
    ssl += __shfl_xor_sync(0xffffffffu, ssl, 2);
    ssh += __shfl_xor_sync(0xffffffffu, ssh, 1);
    ssh += __shfl_xor_sync(0xffffffffu, ssh, 2);
    if (q == 0) {
        inv_out[r0]     = 1.f / fmaxf(sqrtf(ssl), 1e-12f);
        inv_out[r0 + 8] = 1.f / fmaxf(sqrtf(ssh), 1e-12f);
    }
}

// ---------------------------------------------------------------------------
// final launch: out[u] = ue[u] + sum_l ego_l[u] * inv_l[u].
// Egos: B = layer1, C = layer2, A = layer3. Re-zeroes g_cnt / g_ctr.
// ---------------------------------------------------------------------------
__global__ void k_out(const int* __restrict__ users, const float* __restrict__ ue,
                      float* __restrict__ out) {
    int i = blockIdx.x * blockDim.x + threadIdx.x;
    if (i < NTOT) g_cnt[i] = 0;
    if (i == 0)   g_ctr = 0;
    if (i >= BATCH * EMB) return;
    int row = i >> 6, col = i & 63;
    int u = users[row];
    const __half* e1 = reinterpret_cast<const __half*>(g_egoB);
    const __half* e2 = reinterpret_cast<const __half*>(g_egoC);
    const __half* e3 = reinterpret_cast<const __half*>(g_egoA);
    size_t idx = (size_t)u * EMB + col;
    out[i] = ue[idx]
           + __half2float(e1[idx]) * g_inv[0][u]
           + __half2float(e2[idx]) * g_inv[1][u]
           + __half2float(e3[idx]) * g_inv[2][u];
}

// ---------------------------------------------------------------------------
extern "C" void kernel_launch(void* const* d_in, const int* in_sizes, int n_in,
                              void* d_out, int out_size) {
    const int*   users = (const int*)d_in[0];
    const int*   rows  = (const int*)d_in[1];
    const int*   cols  = (const int*)d_in[2];
    const float* vals  = (const float*)d_in[3];
    const float* ue    = (const float*)d_in[4];
    const float* ie    = (const float*)d_in[5];
    const float* Wl[3] = {(const float*)d_in[6], (const float*)d_in[8],  (const float*)d_in[10]};
    const float* Bl[3] = {(const float*)d_in[7], (const float*)d_in[9],  (const float*)d_in[11]};

    __half2 *egoA, *egoB, *egoC;
    float* invBase;
    cudaGetSymbolAddress((void**)&egoA, g_egoA);
    cudaGetSymbolAddress((void**)&egoB, g_egoB);
    cudaGetSymbolAddress((void**)&egoC, g_egoC);
    cudaGetSymbolAddress((void**)&invBase, g_inv);

    // 0: init + hist; 1: alloc (+pad edges to x8); 2: fill
    k_init_hist<<<(NNZ + 255) / 256, 256>>>((const float4*)ue, (const float4*)ie, rows);
    k_alloc<<<(NTOT + 255) / 256, 256>>>();
    k_fill<<<(NNZ + 255) / 256, 256>>>(rows, cols, vals);

    // layers: gather (launch #3 profiled) + tensor-core dense, x3
    const int GG = (NTOT + 31) / 32;     // gather: 32 rows/block
    const int GD = NTOTP / 128;          // dense: 128 rows/block
    k_gather<<<GG, 256>>>(egoA);
    k_dense <<<GD, 256>>>(egoB, invBase + 0 * NTOTP, Wl[0], Bl[0]);
    k_gather<<<GG, 256>>>(egoB);
    k_dense <<<GD, 256>>>(egoC, invBase + 1 * NTOTP, Wl[1], Bl[1]);
    k_gather<<<GG, 256>>>(egoC);
    k_dense <<<GD, 256>>>(egoA, invBase + 2 * NTOTP, Wl[2], Bl[2]);

    // output gather + counter re-zero
    k_out<<<(BATCH * EMB + 255) / 256, 256>>>(users, ue, (float*)d_out);
}